// round 4
// baseline (speedup 1.0000x reference)
#include <cuda_runtime.h>

#define MAXABS_BLOCKS 2048

// Scratch (written unconditionally each run -> no init kernel needed).
__device__ unsigned int g_partial[MAXABS_BLOCKS];
__device__ unsigned int g_max_bits;
__device__ unsigned int g_ticket;      // zero-initialized; reset each run by last block

// ---------------------------------------------------------------------------
// Pass 1: per-block max|x|, REVERSE traversal (front of x stays in L2 for the
// quant kernel's forward read). 4x unrolled independent loads for MLP.
// Last block folds the 2048-partial reduction (saves a ~3.5us launch).
// ---------------------------------------------------------------------------
__global__ __launch_bounds__(256) void hx_maxabs_kernel(
    const float4* __restrict__ x, int n4) {
    float m = 0.0f;
    const int stride = gridDim.x * blockDim.x;
    int i = blockIdx.x * blockDim.x + threadIdx.x;
    for (; i + 3 * stride < n4; i += 4 * stride) {
        float4 a = x[n4 - 1 - i];
        float4 b = x[n4 - 1 - (i + stride)];
        float4 c = x[n4 - 1 - (i + 2 * stride)];
        float4 d = x[n4 - 1 - (i + 3 * stride)];
        float ma = fmaxf(fmaxf(fabsf(a.x), fabsf(a.y)), fmaxf(fabsf(a.z), fabsf(a.w)));
        float mb = fmaxf(fmaxf(fabsf(b.x), fabsf(b.y)), fmaxf(fabsf(b.z), fabsf(b.w)));
        float mc = fmaxf(fmaxf(fabsf(c.x), fabsf(c.y)), fmaxf(fabsf(c.z), fabsf(c.w)));
        float md = fmaxf(fmaxf(fabsf(d.x), fabsf(d.y)), fmaxf(fabsf(d.z), fabsf(d.w)));
        m = fmaxf(m, fmaxf(fmaxf(ma, mb), fmaxf(mc, md)));
    }
    for (; i < n4; i += stride) {
        float4 v = x[n4 - 1 - i];
        m = fmaxf(m, fmaxf(fmaxf(fabsf(v.x), fabsf(v.y)),
                           fmaxf(fabsf(v.z), fabsf(v.w))));
    }
#pragma unroll
    for (int o = 16; o > 0; o >>= 1)
        m = fmaxf(m, __shfl_xor_sync(0xffffffffu, m, o));
    __shared__ float warpmax[8];
    __shared__ bool is_last;
    const int lane = threadIdx.x & 31, wid = threadIdx.x >> 5;
    if (lane == 0) warpmax[wid] = m;
    __syncthreads();
    if (threadIdx.x == 0) {
        float bm = warpmax[0];
#pragma unroll
        for (int w = 1; w < 8; ++w) bm = fmaxf(bm, warpmax[w]);
        g_partial[blockIdx.x] = __float_as_uint(bm);
        __threadfence();                               // publish partial
        unsigned int t = atomicAdd(&g_ticket, 1u);
        is_last = (t == (unsigned int)(gridDim.x - 1));
    }
    __syncthreads();

    if (is_last) {
        // Final reduction of 2048 partials inside the last-arriving block.
        float r = 0.0f;
#pragma unroll
        for (int k = 0; k < MAXABS_BLOCKS / 256; ++k)
            r = fmaxf(r, __uint_as_float(g_partial[threadIdx.x + 256 * k]));
#pragma unroll
        for (int o = 16; o > 0; o >>= 1)
            r = fmaxf(r, __shfl_xor_sync(0xffffffffu, r, o));
        if (lane == 0) warpmax[wid] = r;
        __syncthreads();
        if (threadIdx.x == 0) {
            float bm = warpmax[0];
#pragma unroll
            for (int w = 1; w < 8; ++w) bm = fmaxf(bm, warpmax[w]);
            g_max_bits = __float_as_uint(bm);
            g_ticket = 0u;                             // graph-replay determinism
        }
    }
}

// Fast tanh: exp2 (MUFU.EX2) + __fdividef (MUFU.RCP + mul), ~2 ulp.
__device__ __forceinline__ float hx_tanh(float x) {
    float ax = fminf(fabsf(x), 30.0f);
    float e  = exp2f(ax * 2.8853900817779268f);     // exp(2*ax)
    float t  = __fdividef(e - 1.0f, e + 1.0f);
    return copysignf(t, x);
}

// ---------------------------------------------------------------------------
// Pass 2: quantize + per-group (8 channels, stride 9) top-4 keep.
// Each block stages 2304 contiguous floats (32 segments of 72 = 8ch x 9hw)
// in SMEM; each of 288 threads owns one group of 8 stride-9 cells.
// ---------------------------------------------------------------------------
__global__ __launch_bounds__(288) void hx_quant_kernel(
    const float* __restrict__ x, float* __restrict__ out,
    const int* __restrict__ bits_ptr) {
    __shared__ __align__(16) float tile[2304];
    const int tid = threadIdx.x;
    const long long blk = (long long)blockIdx.x * 2304;
    const float4* in4 = (const float4*)(x + blk);
    float4* out4 = (float4*)(out + blk);
    float4* t4 = (float4*)tile;

    t4[tid]       = in4[tid];
    t4[tid + 288] = in4[tid + 288];
    __syncthreads();

    const float delta     = (float)((1 << (bits_ptr[0] - 1)) - 1);  // 127
    const float M         = hx_tanh(__uint_as_float(g_max_bits));   // max|tanh|
    const float s         = __fdiv_rn(delta, M);
    const float inv_delta = __fdiv_rn(1.0f, delta);

    const int seg  = tid / 9;          // 0..31
    const int hw   = tid - seg * 9;    // 0..8
    const int base = seg * 72 + hw;

    int iv[8];
    int key[8];
    int rank[8];
#pragma unroll
    for (int k = 0; k < 8; ++k) {
        float t = hx_tanh(tile[base + 9 * k]);
        int v   = __float2int_rn(t * s);            // round-half-even
        iv[k]   = v;
        // larger |v| wins; equal |v| -> lower channel index wins (top_k stable)
        key[k]  = (abs(v) << 3) | (7 - k);
        rank[k] = 0;
    }
#pragma unroll
    for (int i = 0; i < 8; ++i)
#pragma unroll
        for (int j = i + 1; j < 8; ++j) {
            if (key[i] > key[j]) rank[j]++; else rank[i]++;
        }
#pragma unroll
    for (int i = 0; i < 8; ++i) {
        float o = (rank[i] < 4) ? (float)iv[i] * inv_delta : 0.0f;
        tile[base + 9 * i] = o;
    }
    __syncthreads();

    // Streaming stores: out is never re-read; keep x resident in L2.
    __stcs(&out4[tid],       t4[tid]);
    __stcs(&out4[tid + 288], t4[tid + 288]);
}

extern "C" void kernel_launch(void* const* d_in, const int* in_sizes, int n_in,
                              void* d_out, int out_size) {
    const float* x  = (const float*)d_in[0];
    const int* bits = (const int*)d_in[1];
    float* out      = (float*)d_out;

    const int n  = in_sizes[0];          // 37748736
    const int n4 = n >> 2;
    const int qblocks = n / 2304;        // 16384 (exact)

    hx_maxabs_kernel<<<MAXABS_BLOCKS, 256>>>((const float4*)x, n4);
    hx_quant_kernel<<<qblocks, 288>>>(x, out, bits);
}